// round 1
// baseline (speedup 1.0000x reference)
#include <cuda_runtime.h>

#define BB    4
#define NN    2304
#define CC    64
#define NODE_ 48
#define KTOP  11          // K_NEIGS + 1
#define NWIN  22
#define NLOC  484         // 22*22 local hyperedges
#define EPB   (NN + NLOC) // edges per batch = 2788
#define BN    (BB * NN)   // 9216
#define BNEPS 1e-5f

// ---------------- scratch (static device globals; no allocation) -------------
__device__ float g_d[(size_t)BB * NN * NN];      // 84.9 MB distance matrix
__device__ int   g_mem[(size_t)BB * NN * NN];    // edge member lists (cap N)
__device__ int   g_cnt1[BN];                     // Dv: in-degree of 11-NN graph
__device__ int   g_cnt2[BN];                     // knn part of total node degree
__device__ float g_xsq[BN];
__device__ float g_dv2[BN];                      // DV^-0.5
__device__ float g_z[BN * CC];                   // dv2 * (xW^T + b)
__device__ float g_y[BN * CC];                   // conv output
__device__ float g_bns[2 * CC];                  // BN sum / sumsq

// ---------------- zero pass --------------------------------------------------
__global__ void k_zero() {
    int i = blockIdx.x * blockDim.x + threadIdx.x;
    int stride = gridDim.x * blockDim.x;
    for (int k = i; k < BN * CC; k += stride) g_y[k] = 0.f;
    for (int k = i; k < BN; k += stride) { g_cnt1[k] = 0; g_cnt2[k] = 0; }
    if (i < 2 * CC) g_bns[i] = 0.f;
}

// ---------------- row squared norms -----------------------------------------
__global__ void k_xsq(const float* __restrict__ x) {
    int w = (blockIdx.x * blockDim.x + threadIdx.x) >> 5;
    int lane = threadIdx.x & 31;
    if (w >= BN) return;
    float a = x[w * CC + lane];
    float b = x[w * CC + 32 + lane];
    float s = a * a + b * b;
    #pragma unroll
    for (int o = 16; o; o >>= 1) s += __shfl_down_sync(0xffffffffu, s, o);
    if (lane == 0) g_xsq[w] = s;
}

// ---------------- pairwise squared distances (64x64 tiles, 8x8/thread) -------
__global__ void __launch_bounds__(64) k_dist(const float* __restrict__ x) {
    __shared__ float As[64][68];
    __shared__ float Bs[64][68];
    __shared__ float sxi[64], sxj[64];
    int b = blockIdx.z;
    int i0 = blockIdx.y * 64, j0 = blockIdx.x * 64;
    const float* xb = x + (size_t)b * NN * CC;
    int tid = threadIdx.x;

    for (int k = tid; k < 64 * 16; k += 64) {
        int r = k >> 4, c4 = (k & 15) << 2;
        float4 va = *(const float4*)(xb + (size_t)(i0 + r) * CC + c4);
        float4 vb = *(const float4*)(xb + (size_t)(j0 + r) * CC + c4);
        *(float4*)(&As[r][c4]) = va;
        *(float4*)(&Bs[r][c4]) = vb;
    }
    sxi[tid] = g_xsq[b * NN + i0 + tid];
    sxj[tid] = g_xsq[b * NN + j0 + tid];
    __syncthreads();

    int tx = tid & 7, ty = tid >> 3;
    float acc[8][8];
    #pragma unroll
    for (int i = 0; i < 8; i++)
        #pragma unroll
        for (int j = 0; j < 8; j++) acc[i][j] = 0.f;

    #pragma unroll 2
    for (int c = 0; c < 64; c += 4) {
        float4 a[8], bb[8];
        #pragma unroll
        for (int u = 0; u < 8; u++) {
            a[u]  = *(const float4*)(&As[ty + 8 * u][c]);
            bb[u] = *(const float4*)(&Bs[tx + 8 * u][c]);
        }
        #pragma unroll
        for (int i = 0; i < 8; i++)
            #pragma unroll
            for (int j = 0; j < 8; j++)
                acc[i][j] += a[i].x * bb[j].x + a[i].y * bb[j].y +
                             a[i].z * bb[j].z + a[i].w * bb[j].w;
    }

    #pragma unroll
    for (int i = 0; i < 8; i++) {
        int row = i0 + ty + 8 * i;
        float xi = sxi[ty + 8 * i];
        #pragma unroll
        for (int j = 0; j < 8; j++) {
            int col = j0 + tx + 8 * j;
            g_d[((size_t)b * NN + row) * NN + col] = (xi - 2.f * acc[i][j]) + sxj[tx + 8 * j];
        }
    }
}

// ---------------- top-k selection (stable: ties -> lower index) --------------
// mode 0: K = 11 fixed, count in-degree into g_cnt1
// mode 1: K = g_cnt1[row], store members into g_mem, count into g_cnt2
__global__ void __launch_bounds__(256) k_topk(int mode) {
    __shared__ float sv[NN];
    __shared__ float swv[8];
    __shared__ int   swi[8];
    int row = blockIdx.x;
    int nb = (row / NN) * NN;
    int tid = threadIdx.x;
    const float* dr = g_d + (size_t)row * NN;
    for (int i = tid; i < NN; i += 256) sv[i] = dr[i];
    __syncthreads();

    int K = mode ? g_cnt1[row] : KTOP;
    size_t mbase = (size_t)row * NN;
    const float INF = __int_as_float(0x7f800000);

    for (int it = 0; it < K; it++) {
        float bv = INF; int bi = NN;
        for (int i = tid; i < NN; i += 256) {
            float v = sv[i];
            if (v < bv) { bv = v; bi = i; }
        }
        #pragma unroll
        for (int o = 16; o; o >>= 1) {
            float ov = __shfl_down_sync(0xffffffffu, bv, o);
            int   oi = __shfl_down_sync(0xffffffffu, bi, o);
            if (ov < bv || (ov == bv && oi < bi)) { bv = ov; bi = oi; }
        }
        if ((tid & 31) == 0) { swv[tid >> 5] = bv; swi[tid >> 5] = bi; }
        __syncthreads();
        if (tid == 0) {
            float mv = swv[0]; int mi = swi[0];
            #pragma unroll
            for (int w = 1; w < 8; w++)
                if (swv[w] < mv || (swv[w] == mv && swi[w] < mi)) { mv = swv[w]; mi = swi[w]; }
            sv[mi] = INF;
            if (mode) {
                g_mem[mbase + it] = mi;
                atomicAdd(&g_cnt2[nb + mi], 1);
            } else {
                atomicAdd(&g_cnt1[nb + mi], 1);
            }
        }
        __syncthreads();
    }
}

// ---------------- node normalization factors ---------------------------------
__device__ __forceinline__ int coverc(int r) {
    int lo = r - 4; if (lo < 0) lo = 0;
    int hi = r;     if (hi > 42) hi = 42;
    if (hi < lo) return 0;
    return hi / 2 - (lo + 1) / 2 + 1;   // count of even starts in [lo, hi]
}

__global__ void k_dv2() {
    int i = blockIdx.x * blockDim.x + threadIdx.x;
    if (i >= BN) return;
    int n = i % NN;
    int deg = g_cnt2[i] + coverc(n / NODE_) * coverc(n % NODE_);
    g_dv2[i] = rsqrtf((float)deg);
}

// ---------------- z = dv2 * (x W^T + b) --------------------------------------
__global__ void __launch_bounds__(256) k_z(const float* __restrict__ x,
                                           const float* __restrict__ W,
                                           const float* __restrict__ bias) {
    __shared__ float Ws[64][65];
    __shared__ float xs[32][65];
    __shared__ float sb[64];
    int tid = threadIdx.x;
    int base = blockIdx.x * 32;
    for (int k = tid; k < 64 * 64; k += 256) Ws[k >> 6][k & 63] = W[k];
    for (int k = tid; k < 32 * 64; k += 256) xs[k >> 6][k & 63] = x[(size_t)(base + (k >> 6)) * CC + (k & 63)];
    if (tid < 64) sb[tid] = bias[tid];
    __syncthreads();

    int o = tid & 63, rg = tid >> 6;
    for (int r = rg; r < 32; r += 4) {
        float acc = sb[o];
        #pragma unroll
        for (int c = 0; c < 64; c++) acc += xs[r][c] * Ws[o][c];
        int row = base + r;
        g_z[(size_t)row * CC + o] = g_dv2[row] * acc;
    }
}

// ---------------- hyperedge gather / mean / scatter --------------------------
__global__ void __launch_bounds__(64) k_edge() {
    __shared__ int   sm[NN];
    __shared__ float sdv[NN];
    int e = blockIdx.x;
    int b = e / EPB;
    int le = e % EPB;
    int tid = threadIdx.x;
    int m;
    if (le < NN) {                         // knn hyperedge centered at node le
        m = g_cnt1[b * NN + le];
        const int* lst = g_mem + (size_t)(b * NN + le) * NN;
        for (int t = tid; t < m; t += 64) {
            int mi = lst[t];
            sm[t] = mi;
            sdv[t] = g_dv2[b * NN + mi];
        }
    } else {                               // local hyperedge (5x5 window, stride 2)
        int l = le - NN;
        int wi = l / NWIN, wj = l % NWIN;
        m = 25;
        if (tid < 25) {
            int mi = (2 * wi + tid / 5) * NODE_ + (2 * wj + tid % 5);
            sm[tid] = mi;
            sdv[tid] = g_dv2[b * NN + mi];
        }
    }
    __syncthreads();

    float acc = 0.f;
    for (int t = 0; t < m; t++)
        acc += g_z[((size_t)b * NN + sm[t]) * CC + tid];
    float u = acc * (1.0f / (float)m);     // DE = member count
    for (int t = 0; t < m; t++)
        atomicAdd(&g_y[((size_t)b * NN + sm[t]) * CC + tid], sdv[t] * u);
}

// ---------------- batchnorm statistics ---------------------------------------
__global__ void __launch_bounds__(256) k_bnstat() {
    __shared__ float red[256];
    int tid = threadIdx.x;
    int c = tid & 63, rg = tid >> 6;
    int r0 = blockIdx.x * 192;
    float s = 0.f, sq = 0.f;
    for (int r = r0 + rg; r < r0 + 192; r += 4) {
        float v = g_y[(size_t)r * CC + c];
        s += v; sq += v * v;
    }
    red[tid] = s; __syncthreads();
    if (rg == 0) atomicAdd(&g_bns[c], red[tid] + red[tid + 64] + red[tid + 128] + red[tid + 192]);
    __syncthreads();
    red[tid] = sq; __syncthreads();
    if (rg == 0) atomicAdd(&g_bns[64 + c], red[tid] + red[tid + 64] + red[tid + 128] + red[tid + 192]);
}

// ---------------- normalize + relu + residual --------------------------------
__global__ void __launch_bounds__(256) k_final(const float* __restrict__ x,
                                               const float* __restrict__ gamma,
                                               const float* __restrict__ beta,
                                               float* __restrict__ out) {
    __shared__ float sscale[64], sshift[64];
    int tid = threadIdx.x;
    if (tid < 64) {
        float mean = g_bns[tid] * (1.f / (float)BN);
        float var = g_bns[64 + tid] * (1.f / (float)BN) - mean * mean;
        float inv = rsqrtf(var + BNEPS);
        sscale[tid] = gamma[tid] * inv;
        sshift[tid] = beta[tid] - gamma[tid] * mean * inv;
    }
    __syncthreads();
    int idx = blockIdx.x * 256 + tid;   // grid covers exactly BN*CC
    int c = idx & 63;
    float v = g_y[idx] * sscale[c] + sshift[c];
    out[idx] = fmaxf(v, 0.f) + x[idx];
}

// ---------------- launch -----------------------------------------------------
extern "C" void kernel_launch(void* const* d_in, const int* in_sizes, int n_in,
                              void* d_out, int out_size) {
    const float* x     = (const float*)d_in[0];
    const float* W     = (const float*)d_in[1];
    const float* bias  = (const float*)d_in[2];
    const float* gamma = (const float*)d_in[3];
    const float* beta  = (const float*)d_in[4];
    float* out = (float*)d_out;
    (void)in_sizes; (void)n_in; (void)out_size;

    k_zero<<<512, 256>>>();
    k_xsq<<<(BN * 32) / 256, 256>>>(x);
    k_dist<<<dim3(NN / 64, NN / 64, BB), 64>>>(x);
    k_topk<<<BN, 256>>>(0);
    k_topk<<<BN, 256>>>(1);
    k_dv2<<<(BN + 255) / 256, 256>>>();
    k_z<<<BN / 32, 256>>>(x, W, bias);
    k_edge<<<BB * EPB, 64>>>();
    k_bnstat<<<48, 256>>>();
    k_final<<<(BN * CC) / 256, 256>>>(x, gamma, beta, out);
}

// round 2
// speedup vs baseline: 1.1803x; 1.1803x over previous
#include <cuda_runtime.h>

#define BB    4
#define NN    2304
#define CC    64
#define NODE_ 48
#define KTOP  11          // K_NEIGS + 1
#define NWIN  22
#define NLOC  484         // 22*22 local hyperedges
#define EPB   (NN + NLOC) // edges per batch = 2788
#define BN    (BB * NN)   // 9216
#define MSEL  40          // cached top-M per row (fast path)
#define BNEPS 1e-5f

typedef unsigned long long ull;

// ---------------- scratch (static device globals; no allocation) -------------
__device__ unsigned g_du[(size_t)BB * NN * NN]; // ordered-uint distance matrix
__device__ int   g_mem[(size_t)BB * NN * NN];   // slow-path member lists (K>MSEL)
__device__ int   g_top[(size_t)BN * MSEL];      // fast-path sorted top-M indices
__device__ int   g_cnt1[BN];                    // Dv: in-degree of 11-NN graph
__device__ int   g_cnt2[BN];                    // knn part of total node degree
__device__ float g_xsq[BN];
__device__ float g_dv2[BN];                     // DV^-0.5
__device__ float g_z[BN * CC];                  // dv2 * (xW^T + b)
__device__ float g_y[BN * CC];                  // conv output
__device__ float g_bns[2 * CC];                 // BN sum / sumsq

// ---------------- zero pass --------------------------------------------------
__global__ void k_zero() {
    int i = blockIdx.x * blockDim.x + threadIdx.x;
    int stride = gridDim.x * blockDim.x;
    for (int k = i; k < BN * CC; k += stride) g_y[k] = 0.f;
    for (int k = i; k < BN; k += stride) { g_cnt1[k] = 0; g_cnt2[k] = 0; }
    if (i < 2 * CC) g_bns[i] = 0.f;
}

// ---------------- row squared norms -----------------------------------------
__global__ void k_xsq(const float* __restrict__ x) {
    int w = (blockIdx.x * blockDim.x + threadIdx.x) >> 5;
    int lane = threadIdx.x & 31;
    if (w >= BN) return;
    float a = x[w * CC + lane];
    float b = x[w * CC + 32 + lane];
    float s = a * a + b * b;
    #pragma unroll
    for (int o = 16; o; o >>= 1) s += __shfl_down_sync(0xffffffffu, s, o);
    if (lane == 0) g_xsq[w] = s;
}

// float -> order-preserving uint32
__device__ __forceinline__ unsigned fkey(float v) {
    unsigned u = __float_as_uint(v);
    return u ^ ((unsigned)((int)u >> 31) | 0x80000000u);
}

// ---------------- pairwise squared distances: upper triangle only ------------
// 64x64 tiles, 8x8 per thread; writes ordered-uint keys, both orientations.
__global__ void __launch_bounds__(64) k_dist(const float* __restrict__ x) {
    __shared__ float As[64 * 68];
    __shared__ float Bs[64 * 68];
    __shared__ float sxi[64], sxj[64];
    int b = blockIdx.y;
    int t = blockIdx.x;
    int ti = 0;
    while (t >= 36 - ti) { t -= 36 - ti; ti++; }
    int tj = ti + t;
    int i0 = ti * 64, j0 = tj * 64;
    const float* xb = x + (size_t)b * NN * CC;
    int tid = threadIdx.x;

    for (int k = tid; k < 64 * 16; k += 64) {
        int r = k >> 4, c4 = (k & 15) << 2;
        *(float4*)(&As[r * 68 + c4]) = *(const float4*)(xb + (size_t)(i0 + r) * CC + c4);
        *(float4*)(&Bs[r * 68 + c4]) = *(const float4*)(xb + (size_t)(j0 + r) * CC + c4);
    }
    sxi[tid] = g_xsq[b * NN + i0 + tid];
    sxj[tid] = g_xsq[b * NN + j0 + tid];
    __syncthreads();

    int tx = tid & 7, ty = tid >> 3;
    float acc[8][8];
    #pragma unroll
    for (int i = 0; i < 8; i++)
        #pragma unroll
        for (int j = 0; j < 8; j++) acc[i][j] = 0.f;

    #pragma unroll 2
    for (int c = 0; c < 64; c += 4) {
        float4 a[8], bb[8];
        #pragma unroll
        for (int u = 0; u < 8; u++) {
            a[u]  = *(const float4*)(&As[(ty + 8 * u) * 68 + c]);
            bb[u] = *(const float4*)(&Bs[(tx + 8 * u) * 68 + c]);
        }
        #pragma unroll
        for (int i = 0; i < 8; i++)
            #pragma unroll
            for (int j = 0; j < 8; j++)
                acc[i][j] += a[i].x * bb[j].x + a[i].y * bb[j].y +
                             a[i].z * bb[j].z + a[i].w * bb[j].w;
    }

    float xi[8], xj[8];
    #pragma unroll
    for (int u = 0; u < 8; u++) { xi[u] = sxi[ty + 8 * u]; xj[u] = sxj[tx + 8 * u]; }
    __syncthreads();                       // done reading As/Bs; reuse As as stage
    unsigned* S = (unsigned*)As;           // 64x65 staging
    #pragma unroll
    for (int i = 0; i < 8; i++)
        #pragma unroll
        for (int j = 0; j < 8; j++) {
            float v = (xi[i] - 2.f * acc[i][j]) + xj[j];
            S[(ty + 8 * i) * 65 + (tx + 8 * j)] = fkey(v);
        }
    __syncthreads();

    unsigned* dd = g_du + (size_t)b * NN * NN;
    #pragma unroll 4
    for (int r = 0; r < 64; r++)
        dd[(size_t)(i0 + r) * NN + j0 + tid] = S[r * 65 + tid];
    if (ti != tj) {
        #pragma unroll 4
        for (int r = 0; r < 64; r++)
            dd[(size_t)(j0 + r) * NN + i0 + tid] = S[tid * 65 + r];
    }
}

// ---------------- warp-level streaming top-K select --------------------------
#define SENT 0xffffffffffffffffULL

__device__ __forceinline__ void ins4(ull& k1, ull& k2, ull& k3, ull& k4, ull key) {
    if (key < k4) {
        if (key < k3) {
            k4 = k3;
            if (key < k2) {
                k3 = k2;
                if (key < k1) { k2 = k1; k1 = key; } else k2 = key;
            } else k3 = key;
        } else k4 = key;
    }
}

// K extractions, smallest-first by (value, index). Per extracted idx calls SINK.
template <class SINK>
__device__ __forceinline__ void run_select(int row, int lane, int K, SINK sink) {
    const unsigned* dr = g_du + (size_t)row * NN;
    ull k1 = SENT, k2 = SENT, k3 = SENT, k4 = SENT;
    #pragma unroll 3
    for (int t = 0; t < 18; t++) {
        int base = t * 128 + lane * 4;
        uint4 v = *(const uint4*)(dr + base);
        ins4(k1, k2, k3, k4, ((ull)v.x << 32) | (unsigned)(base + 0));
        ins4(k1, k2, k3, k4, ((ull)v.y << 32) | (unsigned)(base + 1));
        ins4(k1, k2, k3, k4, ((ull)v.z << 32) | (unsigned)(base + 2));
        ins4(k1, k2, k3, k4, ((ull)v.w << 32) | (unsigned)(base + 3));
    }
    ull last = 0;
    for (int it = 0; it < K; it++) {
        bool need = (k1 == SENT);
        if (__ballot_sync(0xffffffffu, need)) {
            if (need) {
                k2 = k3 = k4 = SENT;
                for (int t = 0; t < 18; t++) {
                    int base = t * 128 + lane * 4;
                    uint4 v = *(const uint4*)(dr + base);
                    ull a = ((ull)v.x << 32) | (unsigned)(base + 0);
                    ull b = ((ull)v.y << 32) | (unsigned)(base + 1);
                    ull c = ((ull)v.z << 32) | (unsigned)(base + 2);
                    ull d = ((ull)v.w << 32) | (unsigned)(base + 3);
                    if (a > last) ins4(k1, k2, k3, k4, a);
                    if (b > last) ins4(k1, k2, k3, k4, b);
                    if (c > last) ins4(k1, k2, k3, k4, c);
                    if (d > last) ins4(k1, k2, k3, k4, d);
                }
            }
        }
        ull bst = k1;
        #pragma unroll
        for (int o = 16; o; o >>= 1) {
            ull ob = __shfl_down_sync(0xffffffffu, bst, o);
            if (ob < bst) bst = ob;
        }
        bst = __shfl_sync(0xffffffffu, bst, 0);
        last = bst;
        if (k1 == bst) { k1 = k2; k2 = k3; k3 = k4; k4 = SENT; }
        if (lane == 0) sink(it, (int)(unsigned)bst);
    }
}

// fast path: extract MSEL smallest per row; store list; count in-degree (top-11)
__global__ void __launch_bounds__(256) k_select() {
    int row  = blockIdx.x * 8 + (threadIdx.x >> 5);
    int lane = threadIdx.x & 31;
    int nb   = (row / NN) * NN;
    run_select(row, lane, MSEL, [&](int it, int bi) {
        g_top[(size_t)row * MSEL + it] = bi;
        if (it < KTOP) atomicAdd(&g_cnt1[nb + bi], 1);
    });
}

// cnt2 counting; rows with K > MSEL re-select fully into g_mem (slow path)
__global__ void __launch_bounds__(256) k_cnt2slow() {
    int row  = blockIdx.x * 8 + (threadIdx.x >> 5);
    int lane = threadIdx.x & 31;
    int K  = g_cnt1[row];
    int nb = (row / NN) * NN;
    if (K <= MSEL) {
        const int* lst = g_top + (size_t)row * MSEL;
        for (int t = lane; t < K; t += 32) atomicAdd(&g_cnt2[nb + lst[t]], 1);
    } else {
        int* out = g_mem + (size_t)row * NN;
        run_select(row, lane, K, [&](int it, int bi) {
            out[it] = bi;
            atomicAdd(&g_cnt2[nb + bi], 1);
        });
    }
}

// ---------------- node normalization factors ---------------------------------
__device__ __forceinline__ int coverc(int r) {
    int lo = r - 4; if (lo < 0) lo = 0;
    int hi = r;     if (hi > 42) hi = 42;
    if (hi < lo) return 0;
    return hi / 2 - (lo + 1) / 2 + 1;
}

__global__ void k_dv2() {
    int i = blockIdx.x * blockDim.x + threadIdx.x;
    if (i >= BN) return;
    int n = i % NN;
    int deg = g_cnt2[i] + coverc(n / NODE_) * coverc(n % NODE_);
    g_dv2[i] = rsqrtf((float)deg);
}

// ---------------- z = dv2 * (x W^T + b) --------------------------------------
__global__ void __launch_bounds__(256) k_z(const float* __restrict__ x,
                                           const float* __restrict__ W,
                                           const float* __restrict__ bias) {
    __shared__ float Ws[64][65];
    __shared__ float xs[32][65];
    __shared__ float sb[64];
    int tid = threadIdx.x;
    int base = blockIdx.x * 32;
    for (int k = tid; k < 64 * 64; k += 256) Ws[k >> 6][k & 63] = W[k];
    for (int k = tid; k < 32 * 64; k += 256) xs[k >> 6][k & 63] = x[(size_t)(base + (k >> 6)) * CC + (k & 63)];
    if (tid < 64) sb[tid] = bias[tid];
    __syncthreads();

    int o = tid & 63, rg = tid >> 6;
    for (int r = rg; r < 32; r += 4) {
        float acc = sb[o];
        #pragma unroll
        for (int c = 0; c < 64; c++) acc += xs[r][c] * Ws[o][c];
        int row = base + r;
        g_z[(size_t)row * CC + o] = g_dv2[row] * acc;
    }
}

// ---------------- hyperedge gather / mean / scatter --------------------------
__global__ void __launch_bounds__(64) k_edge() {
    __shared__ int   sm[128];
    __shared__ float sdv[128];
    int e = blockIdx.x;
    int b = e / EPB;
    int le = e % EPB;
    int tid = threadIdx.x;
    int bNN = b * NN;
    int m;
    const int* lst = 0;
    if (le < NN) {
        int row = bNN + le;
        m = g_cnt1[row];
        lst = (m <= MSEL) ? (g_top + (size_t)row * MSEL) : (g_mem + (size_t)row * NN);
    } else {
        m = 25;
    }

    if (m <= 128) {
        if (le < NN) {
            for (int t = tid; t < m; t += 64) {
                int mi = lst[t];
                sm[t] = mi;
                sdv[t] = g_dv2[bNN + mi];
            }
        } else {
            int l = le - NN;
            int wi = l / NWIN, wj = l % NWIN;
            if (tid < 25) {
                int mi = (2 * wi + tid / 5) * NODE_ + (2 * wj + tid % 5);
                sm[tid] = mi;
                sdv[tid] = g_dv2[bNN + mi];
            }
        }
        __syncthreads();
        float acc = 0.f;
        for (int t = 0; t < m; t++)
            acc += g_z[((size_t)(bNN + sm[t])) * CC + tid];
        float u = acc * (1.0f / (float)m);
        for (int t = 0; t < m; t++)
            atomicAdd(&g_y[((size_t)(bNN + sm[t])) * CC + tid], sdv[t] * u);
    } else {
        // chunked slow path (m > 128): gather pass + scatter pass
        float acc = 0.f;
        for (int base = 0; base < m; base += 128) {
            int cnt = min(128, m - base);
            __syncthreads();
            for (int t = tid; t < cnt; t += 64) sm[t] = lst[base + t];
            __syncthreads();
            for (int t = 0; t < cnt; t++)
                acc += g_z[((size_t)(bNN + sm[t])) * CC + tid];
        }
        float u = acc * (1.0f / (float)m);
        for (int base = 0; base < m; base += 128) {
            int cnt = min(128, m - base);
            __syncthreads();
            for (int t = tid; t < cnt; t += 64) {
                int mi = lst[base + t];
                sm[t] = mi;
                sdv[t] = g_dv2[bNN + mi];
            }
            __syncthreads();
            for (int t = 0; t < cnt; t++)
                atomicAdd(&g_y[((size_t)(bNN + sm[t])) * CC + tid], sdv[t] * u);
        }
    }
}

// ---------------- batchnorm statistics ---------------------------------------
__global__ void __launch_bounds__(256) k_bnstat() {
    __shared__ float red[256];
    int tid = threadIdx.x;
    int c = tid & 63, rg = tid >> 6;
    int r0 = blockIdx.x * 192;
    float s = 0.f, sq = 0.f;
    for (int r = r0 + rg; r < r0 + 192; r += 4) {
        float v = g_y[(size_t)r * CC + c];
        s += v; sq += v * v;
    }
    red[tid] = s; __syncthreads();
    if (rg == 0) atomicAdd(&g_bns[c], red[tid] + red[tid + 64] + red[tid + 128] + red[tid + 192]);
    __syncthreads();
    red[tid] = sq; __syncthreads();
    if (rg == 0) atomicAdd(&g_bns[64 + c], red[tid] + red[tid + 64] + red[tid + 128] + red[tid + 192]);
}

// ---------------- normalize + relu + residual --------------------------------
__global__ void __launch_bounds__(256) k_final(const float* __restrict__ x,
                                               const float* __restrict__ gamma,
                                               const float* __restrict__ beta,
                                               float* __restrict__ out) {
    __shared__ float sscale[64], sshift[64];
    int tid = threadIdx.x;
    if (tid < 64) {
        float mean = g_bns[tid] * (1.f / (float)BN);
        float var = g_bns[64 + tid] * (1.f / (float)BN) - mean * mean;
        float inv = rsqrtf(var + BNEPS);
        sscale[tid] = gamma[tid] * inv;
        sshift[tid] = beta[tid] - gamma[tid] * mean * inv;
    }
    __syncthreads();
    int idx = blockIdx.x * 256 + tid;
    int c = idx & 63;
    float v = g_y[idx] * sscale[c] + sshift[c];
    out[idx] = fmaxf(v, 0.f) + x[idx];
}

// ---------------- launch -----------------------------------------------------
extern "C" void kernel_launch(void* const* d_in, const int* in_sizes, int n_in,
                              void* d_out, int out_size) {
    const float* x     = (const float*)d_in[0];
    const float* W     = (const float*)d_in[1];
    const float* bias  = (const float*)d_in[2];
    const float* gamma = (const float*)d_in[3];
    const float* beta  = (const float*)d_in[4];
    float* out = (float*)d_out;
    (void)in_sizes; (void)n_in; (void)out_size;

    k_zero<<<512, 256>>>();
    k_xsq<<<(BN * 32) / 256, 256>>>(x);
    k_dist<<<dim3(666, BB), 64>>>(x);
    k_select<<<BN / 8, 256>>>();
    k_cnt2slow<<<BN / 8, 256>>>();
    k_dv2<<<(BN + 255) / 256, 256>>>();
    k_z<<<BN / 32, 256>>>(x, W, bias);
    k_edge<<<BB * EPB, 64>>>();
    k_bnstat<<<48, 256>>>();
    k_final<<<(BN * CC) / 256, 256>>>(x, gamma, beta, out);
}

// round 3
// speedup vs baseline: 1.2881x; 1.0914x over previous
#include <cuda_runtime.h>

#define BB    4
#define NN    2304
#define CC    64
#define NODE_ 48
#define KTOP  11          // K_NEIGS + 1
#define NWIN  22
#define NLOC  484         // 22*22 local hyperedges
#define EPB   (NN + NLOC) // edges per batch = 2788
#define BN    (BB * NN)   // 9216
#define MSEL  40          // cached top-M per row (fast path)
#define BNEPS 1e-5f

typedef unsigned long long ull;

// ---------------- scratch (static device globals; no allocation) -------------
__device__ unsigned g_du[(size_t)BB * NN * NN]; // ordered-uint distance matrix
__device__ int   g_mem[(size_t)BB * NN * NN];   // slow-path member lists (K>MSEL)
__device__ int   g_top[(size_t)BN * MSEL];      // fast-path sorted top-M indices
__device__ int   g_cnt1[BN];                    // Dv: in-degree of 11-NN graph
__device__ int   g_cnt2[BN];                    // knn part of total node degree
__device__ float g_xsq[BN];
__device__ float g_dv2[BN];                     // DV^-0.5
__device__ float g_z[BN * CC];                  // dv2 * (xW^T + b)
__device__ float g_y[BN * CC];                  // conv output
__device__ float g_bns[2 * CC];                 // BN sum / sumsq

// ---------------- zero pass --------------------------------------------------
__global__ void k_zero() {
    int i = blockIdx.x * blockDim.x + threadIdx.x;
    int stride = gridDim.x * blockDim.x;
    for (int k = i; k < BN * CC; k += stride) g_y[k] = 0.f;
    for (int k = i; k < BN; k += stride) { g_cnt1[k] = 0; g_cnt2[k] = 0; }
    if (i < 2 * CC) g_bns[i] = 0.f;
}

// ---------------- row squared norms -----------------------------------------
__global__ void k_xsq(const float* __restrict__ x) {
    int w = (blockIdx.x * blockDim.x + threadIdx.x) >> 5;
    int lane = threadIdx.x & 31;
    if (w >= BN) return;
    float a = x[w * CC + lane];
    float b = x[w * CC + 32 + lane];
    float s = a * a + b * b;
    #pragma unroll
    for (int o = 16; o; o >>= 1) s += __shfl_down_sync(0xffffffffu, s, o);
    if (lane == 0) g_xsq[w] = s;
}

// float -> order-preserving uint32
__device__ __forceinline__ unsigned fkey(float v) {
    unsigned u = __float_as_uint(v);
    return u ^ ((unsigned)((int)u >> 31) | 0x80000000u);
}

// ---------------- pairwise squared distances: upper triangle only ------------
__global__ void __launch_bounds__(64) k_dist(const float* __restrict__ x) {
    __shared__ float As[64 * 68];
    __shared__ float Bs[64 * 68];
    __shared__ float sxi[64], sxj[64];
    int b = blockIdx.y;
    int t = blockIdx.x;
    int ti = 0;
    while (t >= 36 - ti) { t -= 36 - ti; ti++; }
    int tj = ti + t;
    int i0 = ti * 64, j0 = tj * 64;
    const float* xb = x + (size_t)b * NN * CC;
    int tid = threadIdx.x;

    for (int k = tid; k < 64 * 16; k += 64) {
        int r = k >> 4, c4 = (k & 15) << 2;
        *(float4*)(&As[r * 68 + c4]) = *(const float4*)(xb + (size_t)(i0 + r) * CC + c4);
        *(float4*)(&Bs[r * 68 + c4]) = *(const float4*)(xb + (size_t)(j0 + r) * CC + c4);
    }
    sxi[tid] = g_xsq[b * NN + i0 + tid];
    sxj[tid] = g_xsq[b * NN + j0 + tid];
    __syncthreads();

    int tx = tid & 7, ty = tid >> 3;
    float acc[8][8];
    #pragma unroll
    for (int i = 0; i < 8; i++)
        #pragma unroll
        for (int j = 0; j < 8; j++) acc[i][j] = 0.f;

    #pragma unroll 2
    for (int c = 0; c < 64; c += 4) {
        float4 a[8], bb[8];
        #pragma unroll
        for (int u = 0; u < 8; u++) {
            a[u]  = *(const float4*)(&As[(ty + 8 * u) * 68 + c]);
            bb[u] = *(const float4*)(&Bs[(tx + 8 * u) * 68 + c]);
        }
        #pragma unroll
        for (int i = 0; i < 8; i++)
            #pragma unroll
            for (int j = 0; j < 8; j++)
                acc[i][j] += a[i].x * bb[j].x + a[i].y * bb[j].y +
                             a[i].z * bb[j].z + a[i].w * bb[j].w;
    }

    float xi[8], xj[8];
    #pragma unroll
    for (int u = 0; u < 8; u++) { xi[u] = sxi[ty + 8 * u]; xj[u] = sxj[tx + 8 * u]; }
    __syncthreads();
    unsigned* S = (unsigned*)As;           // 64x65 staging
    #pragma unroll
    for (int i = 0; i < 8; i++)
        #pragma unroll
        for (int j = 0; j < 8; j++) {
            float v = (xi[i] - 2.f * acc[i][j]) + xj[j];
            S[(ty + 8 * i) * 65 + (tx + 8 * j)] = fkey(v);
        }
    __syncthreads();

    unsigned* dd = g_du + (size_t)b * NN * NN;
    #pragma unroll 4
    for (int r = 0; r < 64; r++)
        dd[(size_t)(i0 + r) * NN + j0 + tid] = S[r * 65 + tid];
    if (ti != tj) {
        #pragma unroll 4
        for (int r = 0; r < 64; r++)
            dd[(size_t)(j0 + r) * NN + i0 + tid] = S[tid * 65 + r];
    }
}

// ---------------- warp-level streaming top-K select --------------------------
#define SENT 0xffffffffffffffffULL

__device__ __forceinline__ void ins4(ull& k1, ull& k2, ull& k3, ull& k4, ull key) {
    if (key < k4) {
        if (key < k3) {
            k4 = k3;
            if (key < k2) {
                k3 = k2;
                if (key < k1) { k2 = k1; k1 = key; } else k2 = key;
            } else k3 = key;
        } else k4 = key;
    }
}

// warp-wide u64 min via two hardware redux.sync ops (exact (value,index) order)
__device__ __forceinline__ ull warp_min64(ull k) {
    unsigned hi = (unsigned)(k >> 32);
    unsigned bhi = __reduce_min_sync(0xffffffffu, hi);
    unsigned lo = (hi == bhi) ? (unsigned)k : 0xffffffffu;
    unsigned blo = __reduce_min_sync(0xffffffffu, lo);
    return ((ull)bhi << 32) | blo;
}

// K extractions, smallest-first by (value, index). Per extracted idx calls SINK.
template <class SINK>
__device__ __forceinline__ void run_select(int row, int lane, int K, SINK sink) {
    const unsigned* dr = g_du + (size_t)row * NN;
    ull k1 = SENT, k2 = SENT, k3 = SENT, k4 = SENT;
    #pragma unroll 3
    for (int t = 0; t < 18; t++) {
        int base = t * 128 + lane * 4;
        uint4 v = *(const uint4*)(dr + base);
        ins4(k1, k2, k3, k4, ((ull)v.x << 32) | (unsigned)(base + 0));
        ins4(k1, k2, k3, k4, ((ull)v.y << 32) | (unsigned)(base + 1));
        ins4(k1, k2, k3, k4, ((ull)v.z << 32) | (unsigned)(base + 2));
        ins4(k1, k2, k3, k4, ((ull)v.w << 32) | (unsigned)(base + 3));
    }
    ull last = 0;
    for (int it = 0; it < K; it++) {
        bool need = (k1 == SENT);
        if (__ballot_sync(0xffffffffu, need)) {
            if (need) {
                k2 = k3 = k4 = SENT;
                for (int t = 0; t < 18; t++) {
                    int base = t * 128 + lane * 4;
                    uint4 v = *(const uint4*)(dr + base);
                    ull a = ((ull)v.x << 32) | (unsigned)(base + 0);
                    ull b = ((ull)v.y << 32) | (unsigned)(base + 1);
                    ull c = ((ull)v.z << 32) | (unsigned)(base + 2);
                    ull d = ((ull)v.w << 32) | (unsigned)(base + 3);
                    if (a > last) ins4(k1, k2, k3, k4, a);
                    if (b > last) ins4(k1, k2, k3, k4, b);
                    if (c > last) ins4(k1, k2, k3, k4, c);
                    if (d > last) ins4(k1, k2, k3, k4, d);
                }
            }
        }
        ull bst = warp_min64(k1);
        last = bst;
        if (k1 == bst) { k1 = k2; k2 = k3; k3 = k4; k4 = SENT; }
        if (lane == 0) sink(it, (int)(unsigned)bst);
    }
}

// fast path: extract MSEL smallest per row; store list; count in-degree (top-11)
__global__ void __launch_bounds__(256) k_select() {
    int row  = blockIdx.x * 8 + (threadIdx.x >> 5);
    int lane = threadIdx.x & 31;
    int nb   = (row / NN) * NN;
    run_select(row, lane, MSEL, [&](int it, int bi) {
        g_top[(size_t)row * MSEL + it] = bi;
        if (it < KTOP) atomicAdd(&g_cnt1[nb + bi], 1);
    });
}

// cnt2 counting; rows with K > MSEL re-select fully into g_mem (slow path)
__global__ void __launch_bounds__(256) k_cnt2slow() {
    int row  = blockIdx.x * 8 + (threadIdx.x >> 5);
    int lane = threadIdx.x & 31;
    int K  = g_cnt1[row];
    int nb = (row / NN) * NN;
    if (K <= MSEL) {
        const int* lst = g_top + (size_t)row * MSEL;
        for (int t = lane; t < K; t += 32) atomicAdd(&g_cnt2[nb + lst[t]], 1);
    } else {
        int* out = g_mem + (size_t)row * NN;
        run_select(row, lane, K, [&](int it, int bi) {
            out[it] = bi;
            atomicAdd(&g_cnt2[nb + bi], 1);
        });
    }
}

// ---------------- node normalization factors ---------------------------------
__device__ __forceinline__ int coverc(int r) {
    int lo = r - 4; if (lo < 0) lo = 0;
    int hi = r;     if (hi > 42) hi = 42;
    if (hi < lo) return 0;
    return hi / 2 - (lo + 1) / 2 + 1;
}

__global__ void k_dv2() {
    int i = blockIdx.x * blockDim.x + threadIdx.x;
    if (i >= BN) return;
    int n = i % NN;
    int deg = g_cnt2[i] + coverc(n / NODE_) * coverc(n % NODE_);
    g_dv2[i] = rsqrtf((float)deg);
}

// ---------------- z = dv2 * (x W^T + b) --------------------------------------
__global__ void __launch_bounds__(256) k_z(const float* __restrict__ x,
                                           const float* __restrict__ W,
                                           const float* __restrict__ bias) {
    __shared__ float Ws[64][65];
    __shared__ float xs[32][65];
    __shared__ float sb[64];
    int tid = threadIdx.x;
    int base = blockIdx.x * 32;
    for (int k = tid; k < 64 * 64; k += 256) Ws[k >> 6][k & 63] = W[k];
    for (int k = tid; k < 32 * 64; k += 256) xs[k >> 6][k & 63] = x[(size_t)(base + (k >> 6)) * CC + (k & 63)];
    if (tid < 64) sb[tid] = bias[tid];
    __syncthreads();

    int o = tid & 63, rg = tid >> 6;
    for (int r = rg; r < 32; r += 4) {
        float acc = sb[o];
        #pragma unroll
        for (int c = 0; c < 64; c++) acc += xs[r][c] * Ws[o][c];
        int row = base + r;
        g_z[(size_t)row * CC + o] = g_dv2[row] * acc;
    }
}

// ---------------- hyperedge gather / mean / scatter --------------------------
__global__ void __launch_bounds__(64) k_edge() {
    __shared__ int   sm[128];
    __shared__ float sdv[128];
    int e = blockIdx.x;
    int b = e / EPB;
    int le = e % EPB;
    int tid = threadIdx.x;
    int bNN = b * NN;
    int m;
    const int* lst = 0;
    if (le < NN) {
        int row = bNN + le;
        m = g_cnt1[row];
        lst = (m <= MSEL) ? (g_top + (size_t)row * MSEL) : (g_mem + (size_t)row * NN);
    } else {
        m = 25;
    }

    if (m <= 128) {
        if (le < NN) {
            for (int t = tid; t < m; t += 64) {
                int mi = lst[t];
                sm[t] = mi;
                sdv[t] = g_dv2[bNN + mi];
            }
        } else {
            int l = le - NN;
            int wi = l / NWIN, wj = l % NWIN;
            if (tid < 25) {
                int mi = (2 * wi + tid / 5) * NODE_ + (2 * wj + tid % 5);
                sm[tid] = mi;
                sdv[tid] = g_dv2[bNN + mi];
            }
        }
        __syncthreads();
        float acc = 0.f;
        for (int t = 0; t < m; t++)
            acc += g_z[((size_t)(bNN + sm[t])) * CC + tid];
        float u = acc * (1.0f / (float)m);
        for (int t = 0; t < m; t++)
            atomicAdd(&g_y[((size_t)(bNN + sm[t])) * CC + tid], sdv[t] * u);
    } else {
        float acc = 0.f;
        for (int base = 0; base < m; base += 128) {
            int cnt = min(128, m - base);
            __syncthreads();
            for (int t = tid; t < cnt; t += 64) sm[t] = lst[base + t];
            __syncthreads();
            for (int t = 0; t < cnt; t++)
                acc += g_z[((size_t)(bNN + sm[t])) * CC + tid];
        }
        float u = acc * (1.0f / (float)m);
        for (int base = 0; base < m; base += 128) {
            int cnt = min(128, m - base);
            __syncthreads();
            for (int t = tid; t < cnt; t += 64) {
                int mi = lst[base + t];
                sm[t] = mi;
                sdv[t] = g_dv2[bNN + mi];
            }
            __syncthreads();
            for (int t = 0; t < cnt; t++)
                atomicAdd(&g_y[((size_t)(bNN + sm[t])) * CC + tid], sdv[t] * u);
        }
    }
}

// ---------------- batchnorm statistics ---------------------------------------
__global__ void __launch_bounds__(256) k_bnstat() {
    __shared__ float red[256];
    int tid = threadIdx.x;
    int c = tid & 63, rg = tid >> 6;
    int r0 = blockIdx.x * 192;
    float s = 0.f, sq = 0.f;
    for (int r = r0 + rg; r < r0 + 192; r += 4) {
        float v = g_y[(size_t)r * CC + c];
        s += v; sq += v * v;
    }
    red[tid] = s; __syncthreads();
    if (rg == 0) atomicAdd(&g_bns[c], red[tid] + red[tid + 64] + red[tid + 128] + red[tid + 192]);
    __syncthreads();
    red[tid] = sq; __syncthreads();
    if (rg == 0) atomicAdd(&g_bns[64 + c], red[tid] + red[tid + 64] + red[tid + 128] + red[tid + 192]);
}

// ---------------- normalize + relu + residual --------------------------------
__global__ void __launch_bounds__(256) k_final(const float* __restrict__ x,
                                               const float* __restrict__ gamma,
                                               const float* __restrict__ beta,
                                               float* __restrict__ out) {
    __shared__ float sscale[64], sshift[64];
    int tid = threadIdx.x;
    if (tid < 64) {
        float mean = g_bns[tid] * (1.f / (float)BN);
        float var = g_bns[64 + tid] * (1.f / (float)BN) - mean * mean;
        float inv = rsqrtf(var + BNEPS);
        sscale[tid] = gamma[tid] * inv;
        sshift[tid] = beta[tid] - gamma[tid] * mean * inv;
    }
    __syncthreads();
    int idx = blockIdx.x * 256 + tid;
    int c = idx & 63;
    float v = g_y[idx] * sscale[c] + sshift[c];
    out[idx] = fmaxf(v, 0.f) + x[idx];
}

// ---------------- launch -----------------------------------------------------
extern "C" void kernel_launch(void* const* d_in, const int* in_sizes, int n_in,
                              void* d_out, int out_size) {
    const float* x     = (const float*)d_in[0];
    const float* W     = (const float*)d_in[1];
    const float* bias  = (const float*)d_in[2];
    const float* gamma = (const float*)d_in[3];
    const float* beta  = (const float*)d_in[4];
    float* out = (float*)d_out;
    (void)in_sizes; (void)n_in; (void)out_size;

    k_zero<<<512, 256>>>();
    k_xsq<<<(BN * 32) / 256, 256>>>(x);
    k_dist<<<dim3(666, BB), 64>>>(x);
    k_select<<<BN / 8, 256>>>();
    k_cnt2slow<<<BN / 8, 256>>>();
    k_dv2<<<(BN + 255) / 256, 256>>>();
    k_z<<<BN / 32, 256>>>(x, W, bias);
    k_edge<<<BB * EPB, 64>>>();
    k_bnstat<<<48, 256>>>();
    k_final<<<(BN * CC) / 256, 256>>>(x, gamma, beta, out);
}